// round 2
// baseline (speedup 1.0000x reference)
#include <cuda_runtime.h>
#include <math.h>

#define NROWS 16384
#define DDIM  256
#define KCB   8192

#define OFF_Q   16384
#define OFF_ST  (16384 + NROWS*DDIM)
#define OFF_SC  (16384 + 2*NROWS*DDIM)

#define TM 64
#define TK 64
#define DC 32
#define SLOTS 64
#define EPS 5e-5f

__device__ float  d_hist[KCB];
__device__ int    d_bidx[NROWS];
__device__ int    d_cnt[NROWS];
__device__ int    d_cand[NROWS * SLOTS];
__device__ double d_sqsum;

// order-preserving float<->int map (no NaNs present)
__device__ __forceinline__ int   fmap(float f)  { int i = __float_as_int(f); return i < 0 ? i ^ 0x7FFFFFFF : i; }
__device__ __forceinline__ float funmap(int u)  { if (u < 0) u ^= 0x7FFFFFFF; return __int_as_float(u); }

// ---------------------------------------------------------------------------
// Kernel 1: zero accumulators
// ---------------------------------------------------------------------------
__global__ void k_init() {
    int i = blockIdx.x * 256 + threadIdx.x;
    if (i < KCB)   d_hist[i] = 0.f;
    if (i < NROWS) d_cnt[i]  = 0;
    if (i == 0)    d_sqsum   = 0.0;
}

// ---------------------------------------------------------------------------
// Kernel 2 (pass 1): max-dot scan, collect candidates within EPS of row max
// ---------------------------------------------------------------------------
__global__ __launch_bounds__(256) void k_scan(const float* __restrict__ lat,
                                              const float* __restrict__ cb) {
    __shared__ __align__(16) float As[DC][TM + 4];
    __shared__ __align__(16) float Bs[DC][TK + 4];
    __shared__ int Rb[TM];

    const int tid = threadIdx.x;
    const int tx = tid & 15, ty = tid >> 4;
    const int rowbase = blockIdx.x * TM;

    if (tid < TM) Rb[tid] = fmap(-3.0e38f);

    const float4* latv = (const float4*)lat;
    const float4* cbv  = (const float4*)cb;

    for (int kt = 0; kt < KCB; kt += TK) {
        float acc[4][4];
#pragma unroll
        for (int j = 0; j < 4; j++)
#pragma unroll
            for (int l = 0; l < 4; l++) acc[j][l] = 0.f;

        for (int dc = 0; dc < DDIM; dc += DC) {
            __syncthreads();
#pragma unroll
            for (int i = 0; i < 2; i++) {
                int s = tid + i * 256;
                int r = s >> 3, q = s & 7;
                float4 v = latv[(size_t)(rowbase + r) * (DDIM / 4) + (dc >> 2) + q];
                As[q * 4 + 0][r] = v.x; As[q * 4 + 1][r] = v.y;
                As[q * 4 + 2][r] = v.z; As[q * 4 + 3][r] = v.w;
            }
#pragma unroll
            for (int i = 0; i < 2; i++) {
                int s = tid + i * 256;
                int r = s >> 3, q = s & 7;
                float4 v = cbv[(size_t)(kt + r) * (DDIM / 4) + (dc >> 2) + q];
                Bs[q * 4 + 0][r] = v.x; Bs[q * 4 + 1][r] = v.y;
                Bs[q * 4 + 2][r] = v.z; Bs[q * 4 + 3][r] = v.w;
            }
            __syncthreads();
#pragma unroll
            for (int dd = 0; dd < DC; dd++) {
                float4 a = *(const float4*)&As[dd][4 * ty];
                float4 b = *(const float4*)&Bs[dd][4 * tx];
                float av[4] = {a.x, a.y, a.z, a.w};
                float bv[4] = {b.x, b.y, b.z, b.w};
#pragma unroll
                for (int j = 0; j < 4; j++)
#pragma unroll
                    for (int l = 0; l < 4; l++)
                        acc[j][l] = fmaf(av[j], bv[l], acc[j][l]);
            }
        }
        // epilogue: update per-row running max, then collect near-max candidates
#pragma unroll
        for (int j = 0; j < 4; j++) {
            int row = 4 * ty + j;
            float m = fmaxf(fmaxf(acc[j][0], acc[j][1]), fmaxf(acc[j][2], acc[j][3]));
            int mm = fmap(m);
            if (mm > Rb[row]) atomicMax(&Rb[row], mm);
        }
        __syncthreads();
#pragma unroll
        for (int j = 0; j < 4; j++) {
            int row = 4 * ty + j;
            float thr = funmap(Rb[row]) - EPS;
#pragma unroll
            for (int l = 0; l < 4; l++) {
                if (acc[j][l] > thr) {
                    int g = rowbase + row;
                    int pos = atomicAdd(&d_cnt[g], 1);
                    if (pos < SLOTS) d_cand[g * SLOTS + pos] = kt + 4 * tx + l;
                }
            }
        }
        __syncthreads();
    }
}

// ---------------------------------------------------------------------------
// Kernel 3 (pass 2): exact re-evaluation of candidates, replicate reference
// rounding: q = fl( fl(xn2 + cn2) - 2*dot_f ), argmin with lowest-index ties.
// One warp per row.
// ---------------------------------------------------------------------------
__global__ __launch_bounds__(256) void k_exact(const float* __restrict__ lat,
                                               const float* __restrict__ cb,
                                               float* __restrict__ out) {
    const int tid = threadIdx.x;
    const int lane = tid & 31, w = tid >> 5;
    const int row = blockIdx.x * 8 + w;

    // cache this row's latent slice (8 floats per lane) + xn2 in double
    float x[8];
    {
        const float4* xr = (const float4*)(lat + (size_t)row * DDIM);
        float4 a = xr[lane * 2], b = xr[lane * 2 + 1];
        x[0]=a.x; x[1]=a.y; x[2]=a.z; x[3]=a.w;
        x[4]=b.x; x[5]=b.y; x[6]=b.z; x[7]=b.w;
    }
    double xs = 0.0;
#pragma unroll
    for (int i = 0; i < 8; i++) xs += (double)x[i] * (double)x[i];
#pragma unroll
    for (int o = 16; o; o >>= 1) xs += __shfl_xor_sync(0xffffffffu, xs, o);
    float xn2 = (float)xs;

    int   n     = d_cnt[row];
    bool  fallb = (n > SLOTS);
    int   ncand = fallb ? KCB : n;

    float bestq = 3.4e38f;
    int   besti = 0;

    for (int c = 0; c < ncand; c++) {
        int idx = fallb ? c : d_cand[row * SLOTS + c];
        const float4* cr = (const float4*)(cb + (size_t)idx * DDIM);
        float4 a = cr[lane * 2], b = cr[lane * 2 + 1];
        float cv[8] = {a.x, a.y, a.z, a.w, b.x, b.y, b.z, b.w};

        // compensated (float-float) dot + plain fp32 codeword norm
        float hi = 0.f, co = 0.f, cn = 0.f;
#pragma unroll
        for (int i = 0; i < 8; i++) {
            float p = __fmul_rn(x[i], cv[i]);
            float e = __fmaf_rn(x[i], cv[i], -p);
            float t = __fadd_rn(hi, p);
            float z = __fsub_rn(t, hi);
            float q2 = __fadd_rn(__fsub_rn(hi, __fsub_rn(t, z)), __fsub_rn(p, z));
            hi = t; co = __fadd_rn(co, __fadd_rn(q2, e));
            cn = __fmaf_rn(cv[i], cv[i], cn);
        }
        // warp reduce (hi, co) as float-float, cn plain
#pragma unroll
        for (int o = 16; o; o >>= 1) {
            float h2 = __shfl_xor_sync(0xffffffffu, hi, o);
            float c2 = __shfl_xor_sync(0xffffffffu, co, o);
            cn += __shfl_xor_sync(0xffffffffu, cn, o);
            float t = __fadd_rn(hi, h2);
            float z = __fsub_rn(t, hi);
            float q2 = __fadd_rn(__fsub_rn(hi, __fsub_rn(t, z)), __fsub_rn(h2, z));
            hi = t; co = __fadd_rn(co, __fadd_rn(c2, q2));
        }
        if (lane == 0) {
            float df = __fadd_rn(hi, co);            // correctly-rounded fp32 dot
            float t1 = __fadd_rn(xn2, cn);           // fl(xn2 + cn2)  (cn2 annihilates)
            float q  = __fadd_rn(t1, -__fmul_rn(2.f, df));  // fl(t1 - 2*dot)
            if (q < bestq || (q == bestq && idx < besti)) { bestq = q; besti = idx; }
        }
    }
    if (lane == 0) {
        d_bidx[row] = besti;
        out[row] = (float)besti;
    }
}

// ---------------------------------------------------------------------------
// Kernel 4: gather codeword -> quantized + st_quantized, MSE partials, histogram
// ---------------------------------------------------------------------------
__global__ __launch_bounds__(256) void k_gather(const float* __restrict__ lat,
                                                const float* __restrict__ mask,
                                                const float* __restrict__ cb,
                                                float* __restrict__ out) {
    __shared__ float wsum[8];
    const int tid = threadIdx.x;
    const int lane = tid & 31, w = tid >> 5;
    const int row = blockIdx.x * 8 + w;

    int idx = d_bidx[row];
    const float4* x = (const float4*)(lat + (size_t)row * DDIM);
    const float4* c = (const float4*)(cb + (size_t)idx * DDIM);
    float4* q  = (float4*)(out + OFF_Q  + (size_t)row * DDIM);
    float4* st = (float4*)(out + OFF_ST + (size_t)row * DDIM);

    float s = 0.f;
#pragma unroll
    for (int i = lane; i < DDIM / 4; i += 32) {
        float4 cv = c[i], xv = x[i];
        q[i]  = cv;
        st[i] = cv;
        float d0 = xv.x - cv.x, d1 = xv.y - cv.y;
        float d2 = xv.z - cv.z, d3 = xv.w - cv.w;
        s += d0 * d0 + d1 * d1 + d2 * d2 + d3 * d3;
    }
#pragma unroll
    for (int o = 16; o; o >>= 1) s += __shfl_xor_sync(0xffffffffu, s, o);
    if (lane == 0) {
        wsum[w] = s;
        atomicAdd(&d_hist[idx], mask[row]);
    }
    __syncthreads();
    if (tid == 0) {
        double t = 0.0;
#pragma unroll
        for (int i = 0; i < 8; i++) t += (double)wsum[i];
        atomicAdd(&d_sqsum, t);
    }
}

// ---------------------------------------------------------------------------
// Kernel 5: finalize losses + perplexity
// ---------------------------------------------------------------------------
__global__ void k_final(const float* __restrict__ mask, float* __restrict__ out) {
    __shared__ float sh[256];
    const int tid = threadIdx.x;

    float m = 0.f;
    for (int i = tid; i < NROWS; i += 256) m += mask[i];
    sh[tid] = m; __syncthreads();
    for (int o = 128; o; o >>= 1) { if (tid < o) sh[tid] += sh[tid + o]; __syncthreads(); }
    float denom = fmaxf(sh[0], 1.0f);
    __syncthreads();

    float e = 0.f;
    for (int k2 = tid; k2 < KCB; k2 += 256) {
        float p = d_hist[k2] / denom;
        e += p * logf(p + 1e-8f);
    }
    sh[tid] = e; __syncthreads();
    for (int o = 128; o; o >>= 1) { if (tid < o) sh[tid] += sh[tid + o]; __syncthreads(); }

    if (tid == 0) {
        double mse = d_sqsum / (double)((size_t)NROWS * DDIM);
        out[OFF_SC + 0] = (float)(mse * 0.25);
        out[OFF_SC + 1] = (float)mse;
        out[OFF_SC + 2] = expf(-sh[0]);
    }
}

// ---------------------------------------------------------------------------
extern "C" void kernel_launch(void* const* d_in, const int* in_sizes, int n_in,
                              void* d_out, int out_size) {
    const float* lat  = (const float*)d_in[0];
    const float* mask = (const float*)d_in[1];
    const float* cb   = (const float*)d_in[2];
    float* out = (float*)d_out;

    k_init  <<<NROWS / 256, 256>>>();
    k_scan  <<<NROWS / TM, 256>>>(lat, cb);
    k_exact <<<NROWS / 8, 256>>>(lat, cb, out);
    k_gather<<<NROWS / 8, 256>>>(lat, mask, cb, out);
    k_final <<<1, 256>>>(mask, out);
}